// round 8
// baseline (speedup 1.0000x reference)
#include <cuda_runtime.h>
#include <cuda_bf16.h>
#include <math.h>

// ---------------- problem constants ----------------
#define TSZ    480000
#define BATCH  8
#define CHUNK  4096
#define STRIDE 3072
#define NCH    157
#define NF     13
#define NFFT   1024
#define HOP    256
#define FBINS  513
#define HDIM   256
#define EDIM   128
#define N3H    768
#define SEQ    (BATCH*NCH)   // 1256
#define ROWS   (SEQ*NF)      // 16328
#define CPB    (NCH*NF)      // 2041
#define KPAD   528
#define PWLD   1152
#define NGB    1026
#define PI_F   3.14159265358979323846f

// ---------------- scratch ----------------
__device__ __nv_bfloat16 g_magh[ROWS*KPAD], g_magl[ROWS*KPAD];
__device__ float g_cosp[ROWS*FBINS];
__device__ float g_sinp[ROWS*FBINS];
__device__ float g_xg  [ROWS*N3H];
__device__ __nv_bfloat16 g_hsh[ROWS*HDIM], g_hsl[ROWS*HDIM];
__device__ float g_gb  [ROWS*NGB];
__device__ float g_y   [ROWS*NFFT];
__device__ float g_embrow[BATCH*N3H];
__device__ float g_wsum[CHUNK];
__device__ __nv_bfloat16 g_wxh[N3H*KPAD], g_wxl[N3H*KPAD];   // [n][k]
__device__ __nv_bfloat16 g_pwh[PWLD*HDIM], g_pwl[PWLD*HDIM]; // [n][k]
__device__ __nv_bfloat16 g_whh[N3H*HDIM], g_whl[N3H*HDIM];   // [n][k], n = gate-natural 0..767
__device__ float g_twr[512], g_twi[512];
__device__ float g_win[NFFT];

__device__ __forceinline__ float sigf(float x) { return 1.f/(1.f + expf(-x)); }

__device__ __forceinline__ void bsplit(float v, __nv_bfloat16& h, __nv_bfloat16& l) {
    h = __float2bfloat16(v);
    l = __float2bfloat16(v - __bfloat162float(h));
}

__device__ __forceinline__ void mmab(float* c, const unsigned* a, unsigned b0, unsigned b1) {
    asm volatile("mma.sync.aligned.m16n8k16.row.col.f32.bf16.bf16.f32 "
        "{%0,%1,%2,%3}, {%4,%5,%6,%7}, {%8,%9}, {%0,%1,%2,%3};"
        : "+f"(c[0]), "+f"(c[1]), "+f"(c[2]), "+f"(c[3])
        : "r"(a[0]), "r"(a[1]), "r"(a[2]), "r"(a[3]), "r"(b0), "r"(b1));
}
__device__ __forceinline__ void cpa16(unsigned d, const void* s, int sz) {
    asm volatile("cp.async.ca.shared.global [%0], [%1], 16, %2;" :: "r"(d), "l"(s), "r"(sz));
}
#define CPA_COMMIT() asm volatile("cp.async.commit_group;")
#define CPA_WAIT()   asm volatile("cp.async.wait_all;" ::: "memory")

// ---------------- merged prep ----------------
#define PB_TAB 16
#define PB_WX  1584   // N3H*KPAD/256
#define PB_PW  1152   // PWLD*HDIM/256
#define PB_WH  768    // N3H*HDIM/256
__global__ void k_prep(const float* __restrict__ wx,
                       const float* __restrict__ pw,
                       const float* __restrict__ wh,
                       const float* __restrict__ emb_table,
                       const int*   __restrict__ effect_id) {
    __shared__ float se[EDIM];
    const int bx = blockIdx.x, tid = threadIdx.x;
    if (bx < PB_TAB) {
        int i = bx*256 + tid;
        if (i < 512) {
            float s, c; sincosf(-(2.f*PI_F/NFFT)*i, &s, &c);
            g_twr[i] = c; g_twi[i] = s;
        }
        if (i < NFFT)
            g_win[i] = 0.5f - 0.5f*cosf((2.f*PI_F/NFFT)*i);
        if (i < CHUNK) {
            float ws = 0.f;
            for (int fi = 0; fi < NF; fi++) {
                int d = i - fi*HOP;
                if (d >= 0 && d < NFFT) {
                    float w = 0.5f - 0.5f*cosf((2.f*PI_F/NFFT)*d);
                    ws += w*w;
                }
            }
            g_wsum[i] = ws;
        }
    } else if (bx < PB_TAB + PB_WX) {
        int i = (bx - PB_TAB)*256 + tid;
        int n = i / KPAD, k = i % KPAD;
        float v = (k < FBINS) ? wx[(size_t)k*N3H + n] : 0.f;
        bsplit(v, g_wxh[i], g_wxl[i]);
    } else if (bx < PB_TAB + PB_WX + PB_PW) {
        int j = (bx - PB_TAB - PB_WX)*256 + tid;
        int n = j / HDIM, k = j % HDIM;
        float v = (n < NGB) ? pw[(size_t)k*NGB + n] : 0.f;
        bsplit(v, g_pwh[j], g_pwl[j]);
    } else if (bx < PB_TAB + PB_WX + PB_PW + PB_WH) {
        int j = (bx - PB_TAB - PB_WX - PB_PW)*256 + tid;
        int n = j >> 8, k = j & 255;
        float v = wh[(size_t)k*N3H + n];
        bsplit(v, g_whh[j], g_whl[j]);
    } else {
        int b = bx - PB_TAB - PB_WX - PB_PW - PB_WH;   // 0..7
        if (tid < EDIM) se[tid] = emb_table[effect_id[b]*EDIM + tid];
        __syncthreads();
        for (int j = tid; j < N3H; j += 256) {
            float acc = 0.f;
            #pragma unroll 8
            for (int k = 0; k < EDIM; k++)
                acc += se[k] * wx[(size_t)(FBINS + k)*N3H + j];
            g_embrow[b*N3H + j] = acc;
        }
    }
}

// ---------------- forward STFT: 2 real frames per complex FFT, radix-4 core ----------------
__global__ void k_fwdfft(const float* __restrict__ audio) {
    __shared__ float sr[NFFT], si[NFFT];
    __shared__ float twr[512], twi[512];
    const int pr  = blockIdx.x;
    const int tid = threadIdx.x;
    const int fr0 = 2*pr, fr1 = fr0 + 1;
    const int b0 = fr0 / CPB, r0 = fr0 % CPB;
    const int b1 = fr1 / CPB, r1 = fr1 % CPB;
    const int base0 = (r0/NF)*STRIDE + (r0%NF)*HOP;
    const int base1 = (r1/NF)*STRIDE + (r1%NF)*HOP;

    for (int k = tid; k < 512; k += 256) { twr[k] = g_twr[k]; twi[k] = g_twi[k]; }
    for (int n = tid; n < NFFT; n += 256) {
        int s0 = base0 + n, s1 = base1 + n;
        float v0 = (s0 < TSZ) ? audio[b0*TSZ + s0] : 0.f;
        float v1 = (s1 < TSZ) ? audio[b1*TSZ + s1] : 0.f;
        float w = g_win[n];
        int j = __brev((unsigned)n) >> 22;
        sr[j] = v0*w; si[j] = v1*w;
    }
    __syncthreads();
    #pragma unroll
    for (int s = 1; s <= 9; s += 2) {
        const int h = 1 << (s-1);
        const int pos = tid & (h-1);
        const int grl = tid >> (s-1);
        const int base = (grl << (s+1)) + pos;
        const float wr1 = twr[pos << (10-s)], wi1 = twi[pos << (10-s)];
        const float wr2 = twr[pos << (9-s)],  wi2 = twi[pos << (9-s)];
        const int e3 = (pos + h) << (9-s);
        const float wr3 = twr[e3], wi3 = twi[e3];
        float x0r = sr[base],       x0i = si[base];
        float x1r = sr[base+h],     x1i = si[base+h];
        float x2r = sr[base+2*h],   x2i = si[base+2*h];
        float x3r = sr[base+3*h],   x3i = si[base+3*h];
        float t1r = wr1*x1r - wi1*x1i, t1i = wr1*x1i + wi1*x1r;
        float u0r = x0r + t1r, u0i = x0i + t1i;
        float u1r = x0r - t1r, u1i = x0i - t1i;
        float t3r = wr1*x3r - wi1*x3i, t3i = wr1*x3i + wi1*x3r;
        float u2r = x2r + t3r, u2i = x2i + t3i;
        float u3r = x2r - t3r, u3i = x2i - t3i;
        float v2r = wr2*u2r - wi2*u2i, v2i = wr2*u2i + wi2*u2r;
        float v3r = wr3*u3r - wi3*u3i, v3i = wr3*u3i + wi3*u3r;
        sr[base]       = u0r + v2r; si[base]       = u0i + v2i;
        sr[base+2*h]   = u0r - v2r; si[base+2*h]   = u0i - v2i;
        sr[base+h]     = u1r + v3r; si[base+h]     = u1i + v3i;
        sr[base+3*h]   = u1r - v3r; si[base+3*h]   = u1i - v3i;
        __syncthreads();
    }
    for (int k = tid; k < KPAD; k += 256) {
        if (k < FBINS) {
            int m = (NFFT - k) & (NFFT-1);
            float rek = sr[k], imk = si[k];
            float rem = sr[m], imm = si[m];
            float re0 = 0.5f*(rek + rem), i0 = 0.5f*(imk - imm);
            float re1 = 0.5f*(imk + imm), i1 = 0.5f*(rem - rek);
            float mag0 = sqrtf(re0*re0 + i0*i0);
            float c0, s0;
            if (mag0 > 1e-30f) { float inv = 1.f/mag0; c0 = re0*inv; s0 = i0*inv; }
            else               { c0 = 1.f; s0 = 0.f; }
            float mag1 = sqrtf(re1*re1 + i1*i1);
            float c1, s1;
            if (mag1 > 1e-30f) { float inv = 1.f/mag1; c1 = re1*inv; s1 = i1*inv; }
            else               { c1 = 1.f; s1 = 0.f; }
            bsplit(mag0, g_magh[fr0*KPAD + k], g_magl[fr0*KPAD + k]);
            bsplit(mag1, g_magh[fr1*KPAD + k], g_magl[fr1*KPAD + k]);
            g_cosp[fr0*FBINS + k] = c0; g_sinp[fr0*FBINS + k] = s0;
            g_cosp[fr1*FBINS + k] = c1; g_sinp[fr1*FBINS + k] = s1;
        } else {
            __nv_bfloat16 z = __float2bfloat16(0.f);
            g_magh[fr0*KPAD + k] = z; g_magl[fr0*KPAD + k] = z;
            g_magh[fr1*KPAD + k] = z; g_magl[fr1*KPAD + k] = z;
        }
    }
}

// ================= bf16-split 3-pass tensor GEMM (validated) =================
#define SM_PLANE (128*12)
#define SM_AH(p,r,c) smem_u[((p)*128 + (r))*12 + (c)]
#define SM_AL(p,r,c) smem_u[SM_PLANE*2 + ((p)*128 + (r))*12 + (c)]
#define SM_BH(p,r,c) smem_u[SM_PLANE*4 + ((p)*128 + (r))*12 + (c)]
#define SM_BL(p,r,c) smem_u[SM_PLANE*6 + ((p)*128 + (r))*12 + (c)]
#define SMEM_GEMM_BYTES (SM_PLANE*8*4)   // 49152

template<int NIT, int KSTRIDE>
__device__ __forceinline__ void gemm_core(
    unsigned* smem_u,
    const __nv_bfloat16* Ah_g, const __nv_bfloat16* Al_g, int a_row_max,
    const __nv_bfloat16* Bh_g, const __nv_bfloat16* Bl_g,
    int m0, int n0, float acc[2][8][4])
{
    const int tid = threadIdx.x;
    const int lane = tid & 31, wid = tid >> 5;
    const int wm = wid >> 1, wn = wid & 1;
    const int grp = lane >> 2, tig = lane & 3;
    const int row = tid >> 1, half = tid & 1;
    const int arow = m0 + row;
    const int asz = (arow < a_row_max) ? 16 : 0;
    const int brow = n0 + row;

    unsigned sbase = (unsigned)__cvta_generic_to_shared(smem_u);
    unsigned off = (row*12 + half*4)*4;
    unsigned dAh = sbase + off;
    unsigned dAl = sbase + SM_PLANE*2*4 + off;
    unsigned dBh = sbase + SM_PLANE*4*4 + off;
    unsigned dBl = sbase + SM_PLANE*6*4 + off;
    const unsigned bufB = 128*12*4;

    cpa16(dAh, Ah_g + (size_t)arow*KSTRIDE + half*8, asz);
    cpa16(dAl, Al_g + (size_t)arow*KSTRIDE + half*8, asz);
    cpa16(dBh, Bh_g + (size_t)brow*KSTRIDE + half*8, 16);
    cpa16(dBl, Bl_g + (size_t)brow*KSTRIDE + half*8, 16);
    CPA_COMMIT();
    CPA_WAIT();
    __syncthreads();

    #pragma unroll 1
    for (int it = 0; it < NIT; it++) {
        int p = it & 1, q = p ^ 1;
        if (it + 1 < NIT) {
            int k0 = (it+1)*16;
            cpa16(dAh + q*bufB, Ah_g + (size_t)arow*KSTRIDE + k0 + half*8, asz);
            cpa16(dAl + q*bufB, Al_g + (size_t)arow*KSTRIDE + k0 + half*8, asz);
            cpa16(dBh + q*bufB, Bh_g + (size_t)brow*KSTRIDE + k0 + half*8, 16);
            cpa16(dBl + q*bufB, Bl_g + (size_t)brow*KSTRIDE + k0 + half*8, 16);
            CPA_COMMIT();
        }
        unsigned afh[2][4], afl[2][4];
        #pragma unroll
        for (int mt = 0; mt < 2; mt++) {
            int rA = wm*32 + mt*16 + grp;
            afh[mt][0] = SM_AH(p, rA,   tig);
            afh[mt][1] = SM_AH(p, rA+8, tig);
            afh[mt][2] = SM_AH(p, rA,   tig+4);
            afh[mt][3] = SM_AH(p, rA+8, tig+4);
            afl[mt][0] = SM_AL(p, rA,   tig);
            afl[mt][1] = SM_AL(p, rA+8, tig);
            afl[mt][2] = SM_AL(p, rA,   tig+4);
            afl[mt][3] = SM_AL(p, rA+8, tig+4);
        }
        #pragma unroll
        for (int nt = 0; nt < 8; nt++) {
            int cB = wn*64 + nt*8 + grp;
            unsigned bh0 = SM_BH(p, cB, tig);
            unsigned bh1 = SM_BH(p, cB, tig+4);
            unsigned bl0 = SM_BL(p, cB, tig);
            unsigned bl1 = SM_BL(p, cB, tig+4);
            #pragma unroll
            for (int mt = 0; mt < 2; mt++) {
                mmab(acc[mt][nt], afh[mt], bh0, bh1);
                mmab(acc[mt][nt], afh[mt], bl0, bl1);
                mmab(acc[mt][nt], afl[mt], bh0, bh1);
            }
        }
        if (it + 1 < NIT) CPA_WAIT();
        __syncthreads();
    }
}

// ---- k_xg ----
__global__ __launch_bounds__(256, 2) void k_xg() {
    extern __shared__ unsigned smem_u[];
    const int tid = threadIdx.x;
    const int lane = tid & 31, wid = tid >> 5;
    const int wm = wid >> 1, wn = wid & 1;
    const int grp = lane >> 2, tig = lane & 3;
    const int m0 = blockIdx.y * 128, n0 = blockIdx.x * 128;
    float acc[2][8][4] = {};
    gemm_core<33, KPAD>(smem_u, g_magh, g_magl, ROWS, g_wxh, g_wxl, m0, n0, acc);
    #pragma unroll
    for (int mt = 0; mt < 2; mt++) {
        #pragma unroll
        for (int nt = 0; nt < 8; nt++) {
            int row0 = m0 + wm*32 + mt*16 + grp;
            int col0 = n0 + wn*64 + nt*8 + 2*tig;
            if (row0 < ROWS) {
                int b = row0 / CPB;
                g_xg[(size_t)row0*N3H + col0  ] = acc[mt][nt][0] + g_embrow[b*N3H + col0  ];
                g_xg[(size_t)row0*N3H + col0+1] = acc[mt][nt][1] + g_embrow[b*N3H + col0+1];
            }
            int row1 = row0 + 8;
            if (row1 < ROWS) {
                int b = row1 / CPB;
                g_xg[(size_t)row1*N3H + col0  ] = acc[mt][nt][2] + g_embrow[b*N3H + col0  ];
                g_xg[(size_t)row1*N3H + col0+1] = acc[mt][nt][3] + g_embrow[b*N3H + col0+1];
            }
        }
    }
}

// ---- k_proj ----
__global__ __launch_bounds__(256, 2) void k_proj(const float* __restrict__ pb) {
    extern __shared__ unsigned smem_u[];
    const int tid = threadIdx.x;
    const int lane = tid & 31, wid = tid >> 5;
    const int wm = wid >> 1, wn = wid & 1;
    const int grp = lane >> 2, tig = lane & 3;
    const int m0 = blockIdx.y * 128, n0 = blockIdx.x * 128;
    float acc[2][8][4] = {};
    gemm_core<16, HDIM>(smem_u, g_hsh, g_hsl, ROWS, g_pwh, g_pwl, m0, n0, acc);
    #pragma unroll
    for (int mt = 0; mt < 2; mt++) {
        #pragma unroll
        for (int nt = 0; nt < 8; nt++) {
            int row0 = m0 + wm*32 + mt*16 + grp;
            int col0 = n0 + wn*64 + nt*8 + 2*tig;
            if (row0 < ROWS) {
                if (col0   < NGB) g_gb[(size_t)row0*NGB + col0  ] = acc[mt][nt][0] + pb[col0  ];
                if (col0+1 < NGB) g_gb[(size_t)row0*NGB + col0+1] = acc[mt][nt][1] + pb[col0+1];
            }
            int row1 = row0 + 8;
            if (row1 < ROWS) {
                if (col0   < NGB) g_gb[(size_t)row1*NGB + col0  ] = acc[mt][nt][2] + pb[col0  ];
                if (col0+1 < NGB) g_gb[(size_t)row1*NGB + col0+1] = acc[mt][nt][3] + pb[col0+1];
            }
        }
    }
}

// ================= fused all-timestep GRU =================
// grid = 40 blocks; block owns 32 seqs x ALL 768 gate cols, loops t=0..12.
// smem (uints): A_H [16 slab][32 row][12] @0 (6144), A_L @6144;
//   B: [2 buf][ BH [768][12] (9216) ; BL (9216) ] @12288.  Total 49152 uints = 192KB.
// hg staging (floats [32][772]) aliases B region after mma completes.
#define GA_L   6144
#define GB     12288
#define GBUF   18432
#define GRU2_SMEM_BYTES (49152*4)   // 196608

__device__ __forceinline__ void gru2_loadB(unsigned sbase, int q, int kc) {
    const int tid = threadIdx.x;
    #pragma unroll
    for (int v = 0; v < 6; v++) {
        int slot = tid + v*256;               // 0..1535
        int row = slot >> 1, half = slot & 1;
        cpa16(sbase + (GB + q*GBUF + row*12 + half*4)*4,
              g_whh + (size_t)row*HDIM + kc*16 + half*8, 16);
    }
    #pragma unroll
    for (int v = 0; v < 6; v++) {
        int slot = tid + v*256;
        int row = slot >> 1, half = slot & 1;
        cpa16(sbase + (GB + q*GBUF + 9216 + row*12 + half*4)*4,
              g_whl + (size_t)row*HDIM + kc*16 + half*8, 16);
    }
}

__global__ __launch_bounds__(256, 1) void k_gru2(const float* __restrict__ gbias) {
    extern __shared__ unsigned su[];
    const int tid = threadIdx.x;
    const int lane = tid & 31, wn = tid >> 5;       // 8 warps, each owns 96 cols
    const int grp = lane >> 2, tig = lane & 3;
    const int sq0 = blockIdx.x * 32;
    unsigned sbase = (unsigned)__cvta_generic_to_shared(su);
    __nv_bfloat16* AHb = (__nv_bfloat16*)su;
    __nv_bfloat16* ALb = (__nv_bfloat16*)(su + GA_L);

    // zero A planes (h(-1) = 0)
    for (int i = tid; i < GB; i += 256) su[i] = 0;
    __syncthreads();

    for (int t = 0; t < NF; t++) {
        gru2_loadB(sbase, 0, 0);
        CPA_COMMIT(); CPA_WAIT(); __syncthreads();
        float acc[2][12][4] = {};
        #pragma unroll 1
        for (int kc = 0; kc < 16; kc++) {
            int p = kc & 1, q = p ^ 1;
            if (kc + 1 < 16) { gru2_loadB(sbase, q, kc+1); CPA_COMMIT(); }
            unsigned afh[2][4], afl[2][4];
            #pragma unroll
            for (int mt = 0; mt < 2; mt++) {
                int rA = kc*32 + mt*16 + grp;
                afh[mt][0] = su[rA*12 + tig];
                afh[mt][1] = su[(rA+8)*12 + tig];
                afh[mt][2] = su[rA*12 + tig + 4];
                afh[mt][3] = su[(rA+8)*12 + tig + 4];
                afl[mt][0] = su[GA_L + rA*12 + tig];
                afl[mt][1] = su[GA_L + (rA+8)*12 + tig];
                afl[mt][2] = su[GA_L + rA*12 + tig + 4];
                afl[mt][3] = su[GA_L + (rA+8)*12 + tig + 4];
            }
            #pragma unroll
            for (int nt = 0; nt < 12; nt++) {
                int n = wn*96 + nt*8 + grp;
                unsigned bh0 = su[GB + p*GBUF + n*12 + tig];
                unsigned bh1 = su[GB + p*GBUF + n*12 + tig + 4];
                unsigned bl0 = su[GB + p*GBUF + 9216 + n*12 + tig];
                unsigned bl1 = su[GB + p*GBUF + 9216 + n*12 + tig + 4];
                #pragma unroll
                for (int mt = 0; mt < 2; mt++) {
                    mmab(acc[mt][nt], afh[mt], bh0, bh1);
                    mmab(acc[mt][nt], afh[mt], bl0, bl1);
                    mmab(acc[mt][nt], afl[mt], bh0, bh1);
                }
            }
            if (kc + 1 < 16) CPA_WAIT();
            __syncthreads();
        }
        // stage hg floats [32][772] into B region
        float* hg = (float*)(su + GB);
        #pragma unroll
        for (int mt = 0; mt < 2; mt++) {
            #pragma unroll
            for (int nt = 0; nt < 12; nt++) {
                int r0 = mt*16 + grp, c0 = wn*96 + nt*8 + 2*tig;
                hg[r0*772 + c0]         = acc[mt][nt][0];
                hg[r0*772 + c0 + 1]     = acc[mt][nt][1];
                hg[(r0+8)*772 + c0]     = acc[mt][nt][2];
                hg[(r0+8)*772 + c0 + 1] = acc[mt][nt][3];
            }
        }
        __syncthreads();
        // fused gates: c = tid (0..255), s = 0..31
        {
            int c = tid;
            int slab = c >> 4;
            int uidx0 = (slab*32)*12 + ((c & 15) >> 1);
            int half = c & 1;
            #pragma unroll 1
            for (int s = 0; s < 32; s++) {
                int sq = sq0 + s;
                if (sq >= SEQ) break;
                const float* xg = g_xg + (size_t)(sq*NF + t)*N3H;
                float z = sigf(xg[c]       + hg[s*772 + c]       + gbias[c]);
                float r = sigf(xg[256 + c] + hg[s*772 + 256 + c] + gbias[256 + c]);
                float n = tanhf(xg[512 + c] + r*(hg[s*772 + 512 + c] + gbias[512 + c]));
                int bidx = (uidx0 + s*12)*2 + half;
                float hp = 0.f;
                if (t > 0) hp = __bfloat162float(AHb[bidx]) + __bfloat162float(ALb[bidx]);
                float h = (1.f - z)*n + z*hp;
                __nv_bfloat16 hh, hl;
                bsplit(h, hh, hl);
                AHb[bidx] = hh; ALb[bidx] = hl;
                size_t gi = (size_t)(sq*NF + t)*HDIM + c;
                g_hsh[gi] = hh; g_hsl[gi] = hl;
            }
        }
        __syncthreads();
    }
}

// ---------------- modulate + inverse FFT (radix-4 core, 2 frames/block) ----------------
__global__ void k_modinv() {
    __shared__ float sre0[FBINS], sim0[FBINS], sre1[FBINS], sim1[FBINS];
    __shared__ float sr[NFFT], si[NFFT];
    __shared__ float twr[512], twi[512];
    const int pr  = blockIdx.x;
    const int tid = threadIdx.x;
    const int fr0 = 2*pr, fr1 = fr0 + 1;

    for (int k = tid; k < 512; k += 256) { twr[k] = g_twr[k]; twi[k] = g_twi[k]; }
    for (int k = tid; k < FBINS; k += 256) {
        float mag0 = __bfloat162float(g_magh[fr0*KPAD + k]) + __bfloat162float(g_magl[fr0*KPAD + k]);
        float mm0 = g_gb[(size_t)fr0*NGB + k]*mag0 + g_gb[(size_t)fr0*NGB + FBINS + k];
        sre0[k] = mm0 * g_cosp[fr0*FBINS + k];
        sim0[k] = mm0 * g_sinp[fr0*FBINS + k];
        float mag1 = __bfloat162float(g_magh[fr1*KPAD + k]) + __bfloat162float(g_magl[fr1*KPAD + k]);
        float mm1 = g_gb[(size_t)fr1*NGB + k]*mag1 + g_gb[(size_t)fr1*NGB + FBINS + k];
        sre1[k] = mm1 * g_cosp[fr1*FBINS + k];
        sim1[k] = mm1 * g_sinp[fr1*FBINS + k];
    }
    __syncthreads();
    for (int n = tid; n < NFFT; n += 256) {
        float zr, zi;
        if (n <= 512) { zr = sre0[n] - sim1[n];         zi = sim0[n] + sre1[n]; }
        else { int m = NFFT - n; zr = sre0[m] + sim1[m]; zi = sre1[m] - sim0[m]; }
        int j = __brev((unsigned)n) >> 22;
        sr[j] = zr; si[j] = zi;
    }
    __syncthreads();
    #pragma unroll
    for (int s = 1; s <= 9; s += 2) {
        const int h = 1 << (s-1);
        const int pos = tid & (h-1);
        const int grl = tid >> (s-1);
        const int base = (grl << (s+1)) + pos;
        const float wr1 = twr[pos << (10-s)], wi1 = -twi[pos << (10-s)];
        const float wr2 = twr[pos << (9-s)],  wi2 = -twi[pos << (9-s)];
        const int e3 = (pos + h) << (9-s);
        const float wr3 = twr[e3], wi3 = -twi[e3];
        float x0r = sr[base],       x0i = si[base];
        float x1r = sr[base+h],     x1i = si[base+h];
        float x2r = sr[base+2*h],   x2i = si[base+2*h];
        float x3r = sr[base+3*h],   x3i = si[base+3*h];
        float t1r = wr1*x1r - wi1*x1i, t1i = wr1*x1i + wi1*x1r;
        float u0r = x0r + t1r, u0i = x0i + t1i;
        float u1r = x0r - t1r, u1i = x0i - t1i;
        float t3r = wr1*x3r - wi1*x3i, t3i = wr1*x3i + wi1*x3r;
        float u2r = x2r + t3r, u2i = x2i + t3i;
        float u3r = x2r - t3r, u3i = x2i - t3i;
        float v2r = wr2*u2r - wi2*u2i, v2i = wr2*u2i + wi2*u2r;
        float v3r = wr3*u3r - wi3*u3i, v3i = wr3*u3i + wi3*u3r;
        sr[base]       = u0r + v2r; si[base]       = u0i + v2i;
        sr[base+2*h]   = u0r - v2r; si[base+2*h]   = u0i - v2i;
        sr[base+h]     = u1r + v3r; si[base+h]     = u1i + v3i;
        sr[base+3*h]   = u1r - v3r; si[base+3*h]   = u1i - v3i;
        __syncthreads();
    }
    const float invn = 1.f/(float)NFFT;
    for (int n = tid; n < NFFT; n += 256) {
        float w = invn*g_win[n];
        g_y[(size_t)fr0*NFFT + n] = sr[n]*w;
        g_y[(size_t)fr1*NFFT + n] = si[n]*w;
    }
}

// ---------------- overlap-add ----------------
__global__ void k_overlap(float* __restrict__ out) {
    const int t = blockIdx.x*blockDim.x + threadIdx.x;
    const int b = blockIdx.y;
    if (t >= TSZ) return;
    int ci_hi = t / STRIDE; if (ci_hi > NCH-1) ci_hi = NCH-1;
    int v = t - (CHUNK - 1);
    int ci_lo = (v <= 0) ? 0 : (v + STRIDE - 1)/STRIDE;
    float acc = 0.f;
    for (int ci = ci_lo; ci <= ci_hi; ci++) {
        int n = t - ci*STRIDE;
        int fi_hi = n >> 8; if (fi_hi > NF-1) fi_hi = NF-1;
        int w = n - (NFFT - 1);
        int fi_lo = (w <= 0) ? 0 : (w + HOP - 1) >> 8;
        float s = 0.f;
        for (int fi = fi_lo; fi <= fi_hi; fi++)
            s += g_y[(size_t)(((b*NCH + ci)*NF) + fi)*NFFT + n - fi*HOP];
        acc += s / fmaxf(g_wsum[n], 1e-8f);
    }
    out[b*TSZ + t] = acc;
}

// ---------------- launch ----------------
extern "C" void kernel_launch(void* const* d_in, const int* in_sizes, int n_in,
                              void* d_out, int out_size) {
    const float* audio     = (const float*)d_in[0];
    const float* emb_table = (const float*)d_in[1];
    const float* gru_wx    = (const float*)d_in[2];
    const float* gru_wh    = (const float*)d_in[3];
    const float* gru_b     = (const float*)d_in[4];
    const float* proj_w    = (const float*)d_in[5];
    const float* proj_b    = (const float*)d_in[6];
    const int*   effect_id = (const int*)  d_in[7];
    float* out = (float*)d_out;

    cudaFuncSetAttribute(k_gru2, cudaFuncAttributeMaxDynamicSharedMemorySize,
                         GRU2_SMEM_BYTES);   // idempotent, host-side, not captured

    k_prep<<<PB_TAB + PB_WX + PB_PW + PB_WH + BATCH, 256>>>(
        gru_wx, proj_w, gru_wh, emb_table, effect_id);                        // 1
    k_fwdfft<<<ROWS/2, 256>>>(audio);                                         // 2
    k_xg<<<dim3(N3H/128, (ROWS + 127)/128), 256, SMEM_GEMM_BYTES>>>();        // 3
    k_gru2<<<(SEQ + 31)/32, 256, GRU2_SMEM_BYTES>>>(gru_b);                   // 4 <- profiled
    k_proj<<<dim3(PWLD/128, (ROWS + 127)/128), 256, SMEM_GEMM_BYTES>>>(proj_b);
    k_modinv<<<ROWS/2, 256>>>();
    k_overlap<<<dim3((TSZ + 255)/256, BATCH), 256>>>(out);
}

// round 9
// speedup vs baseline: 1.4534x; 1.4534x over previous
#include <cuda_runtime.h>
#include <cuda_bf16.h>
#include <math.h>

// ---------------- problem constants ----------------
#define TSZ    480000
#define BATCH  8
#define CHUNK  4096
#define STRIDE 3072
#define NCH    157
#define NF     13
#define NFFT   1024
#define HOP    256
#define FBINS  513
#define HDIM   256
#define EDIM   128
#define N3H    768
#define SEQ    (BATCH*NCH)   // 1256
#define ROWS   (SEQ*NF)      // 16328
#define CPB    (NCH*NF)      // 2041
#define KPAD   528
#define PWLD   1152
#define NGB    1026
#define PI_F   3.14159265358979323846f

// ---------------- scratch ----------------
__device__ __nv_bfloat16 g_magh[ROWS*KPAD], g_magl[ROWS*KPAD];
__device__ float g_cosp[ROWS*FBINS];
__device__ float g_sinp[ROWS*FBINS];
__device__ float g_xg  [ROWS*N3H];
__device__ __nv_bfloat16 g_hsh[ROWS*HDIM], g_hsl[ROWS*HDIM];
__device__ float g_gb  [ROWS*NGB];
__device__ float g_y   [ROWS*NFFT];
__device__ float g_embrow[BATCH*N3H];
__device__ float g_wsum[CHUNK];
__device__ __nv_bfloat16 g_wxh[N3H*KPAD], g_wxl[N3H*KPAD];   // [n][k]
__device__ __nv_bfloat16 g_pwh[PWLD*HDIM], g_pwl[PWLD*HDIM]; // [n][k]
__device__ __nv_bfloat16 g_whh[N3H*HDIM], g_whl[N3H*HDIM];   // [n][k], n gate-natural
__device__ float g_twr[512], g_twi[512];
__device__ float g_win[NFFT];

__device__ __forceinline__ float sigf(float x) { return 1.f/(1.f + expf(-x)); }

__device__ __forceinline__ void bsplit(float v, __nv_bfloat16& h, __nv_bfloat16& l) {
    h = __float2bfloat16(v);
    l = __float2bfloat16(v - __bfloat162float(h));
}

__device__ __forceinline__ void mmab(float* c, const unsigned* a, unsigned b0, unsigned b1) {
    asm volatile("mma.sync.aligned.m16n8k16.row.col.f32.bf16.bf16.f32 "
        "{%0,%1,%2,%3}, {%4,%5,%6,%7}, {%8,%9}, {%0,%1,%2,%3};"
        : "+f"(c[0]), "+f"(c[1]), "+f"(c[2]), "+f"(c[3])
        : "r"(a[0]), "r"(a[1]), "r"(a[2]), "r"(a[3]), "r"(b0), "r"(b1));
}
__device__ __forceinline__ void cpa16(unsigned d, const void* s, int sz) {
    asm volatile("cp.async.ca.shared.global [%0], [%1], 16, %2;" :: "r"(d), "l"(s), "r"(sz));
}
#define CPA_COMMIT() asm volatile("cp.async.commit_group;")
#define CPA_WAIT()   asm volatile("cp.async.wait_all;" ::: "memory")

// ---------------- merged prep ----------------
#define PB_TAB 16
#define PB_WX  1584   // N3H*KPAD/256
#define PB_PW  1152   // PWLD*HDIM/256
#define PB_WH  768    // N3H*HDIM/256
__global__ void k_prep(const float* __restrict__ wx,
                       const float* __restrict__ pw,
                       const float* __restrict__ wh,
                       const float* __restrict__ emb_table,
                       const int*   __restrict__ effect_id) {
    __shared__ float se[EDIM];
    const int bx = blockIdx.x, tid = threadIdx.x;
    if (bx < PB_TAB) {
        int i = bx*256 + tid;
        if (i < 512) {
            float s, c; sincosf(-(2.f*PI_F/NFFT)*i, &s, &c);
            g_twr[i] = c; g_twi[i] = s;
        }
        if (i < NFFT)
            g_win[i] = 0.5f - 0.5f*cosf((2.f*PI_F/NFFT)*i);
        if (i < CHUNK) {
            float ws = 0.f;
            for (int fi = 0; fi < NF; fi++) {
                int d = i - fi*HOP;
                if (d >= 0 && d < NFFT) {
                    float w = 0.5f - 0.5f*cosf((2.f*PI_F/NFFT)*d);
                    ws += w*w;
                }
            }
            g_wsum[i] = ws;
        }
    } else if (bx < PB_TAB + PB_WX) {
        int i = (bx - PB_TAB)*256 + tid;
        int n = i / KPAD, k = i % KPAD;
        float v = (k < FBINS) ? wx[(size_t)k*N3H + n] : 0.f;
        bsplit(v, g_wxh[i], g_wxl[i]);
    } else if (bx < PB_TAB + PB_WX + PB_PW) {
        int j = (bx - PB_TAB - PB_WX)*256 + tid;
        int n = j / HDIM, k = j % HDIM;
        float v = (n < NGB) ? pw[(size_t)k*NGB + n] : 0.f;
        bsplit(v, g_pwh[j], g_pwl[j]);
    } else if (bx < PB_TAB + PB_WX + PB_PW + PB_WH) {
        int j = (bx - PB_TAB - PB_WX - PB_PW)*256 + tid;
        int n = j >> 8, k = j & 255;
        float v = wh[(size_t)k*N3H + n];
        bsplit(v, g_whh[j], g_whl[j]);
    } else {
        int b = bx - PB_TAB - PB_WX - PB_PW - PB_WH;   // 0..7
        if (tid < EDIM) se[tid] = emb_table[effect_id[b]*EDIM + tid];
        __syncthreads();
        for (int j = tid; j < N3H; j += 256) {
            float acc = 0.f;
            #pragma unroll 8
            for (int k = 0; k < EDIM; k++)
                acc += se[k] * wx[(size_t)(FBINS + k)*N3H + j];
            g_embrow[b*N3H + j] = acc;
        }
    }
}

// ---------------- forward STFT: 2 real frames per complex FFT, radix-4 core ----------------
__global__ void k_fwdfft(const float* __restrict__ audio) {
    __shared__ float sr[NFFT], si[NFFT];
    __shared__ float twr[512], twi[512];
    const int pr  = blockIdx.x;
    const int tid = threadIdx.x;
    const int fr0 = 2*pr, fr1 = fr0 + 1;
    const int b0 = fr0 / CPB, r0 = fr0 % CPB;
    const int b1 = fr1 / CPB, r1 = fr1 % CPB;
    const int base0 = (r0/NF)*STRIDE + (r0%NF)*HOP;
    const int base1 = (r1/NF)*STRIDE + (r1%NF)*HOP;

    for (int k = tid; k < 512; k += 256) { twr[k] = g_twr[k]; twi[k] = g_twi[k]; }
    for (int n = tid; n < NFFT; n += 256) {
        int s0 = base0 + n, s1 = base1 + n;
        float v0 = (s0 < TSZ) ? audio[b0*TSZ + s0] : 0.f;
        float v1 = (s1 < TSZ) ? audio[b1*TSZ + s1] : 0.f;
        float w = g_win[n];
        int j = __brev((unsigned)n) >> 22;
        sr[j] = v0*w; si[j] = v1*w;
    }
    __syncthreads();
    #pragma unroll
    for (int s = 1; s <= 9; s += 2) {
        const int h = 1 << (s-1);
        const int pos = tid & (h-1);
        const int grl = tid >> (s-1);
        const int base = (grl << (s+1)) + pos;
        const float wr1 = twr[pos << (10-s)], wi1 = twi[pos << (10-s)];
        const float wr2 = twr[pos << (9-s)],  wi2 = twi[pos << (9-s)];
        const int e3 = (pos + h) << (9-s);
        const float wr3 = twr[e3], wi3 = twi[e3];
        float x0r = sr[base],       x0i = si[base];
        float x1r = sr[base+h],     x1i = si[base+h];
        float x2r = sr[base+2*h],   x2i = si[base+2*h];
        float x3r = sr[base+3*h],   x3i = si[base+3*h];
        float t1r = wr1*x1r - wi1*x1i, t1i = wr1*x1i + wi1*x1r;
        float u0r = x0r + t1r, u0i = x0i + t1i;
        float u1r = x0r - t1r, u1i = x0i - t1i;
        float t3r = wr1*x3r - wi1*x3i, t3i = wr1*x3i + wi1*x3r;
        float u2r = x2r + t3r, u2i = x2i + t3i;
        float u3r = x2r - t3r, u3i = x2i - t3i;
        float v2r = wr2*u2r - wi2*u2i, v2i = wr2*u2i + wi2*u2r;
        float v3r = wr3*u3r - wi3*u3i, v3i = wr3*u3i + wi3*u3r;
        sr[base]       = u0r + v2r; si[base]       = u0i + v2i;
        sr[base+2*h]   = u0r - v2r; si[base+2*h]   = u0i - v2i;
        sr[base+h]     = u1r + v3r; si[base+h]     = u1i + v3i;
        sr[base+3*h]   = u1r - v3r; si[base+3*h]   = u1i - v3i;
        __syncthreads();
    }
    for (int k = tid; k < KPAD; k += 256) {
        if (k < FBINS) {
            int m = (NFFT - k) & (NFFT-1);
            float rek = sr[k], imk = si[k];
            float rem = sr[m], imm = si[m];
            float re0 = 0.5f*(rek + rem), i0 = 0.5f*(imk - imm);
            float re1 = 0.5f*(imk + imm), i1 = 0.5f*(rem - rek);
            float mag0 = sqrtf(re0*re0 + i0*i0);
            float c0, s0;
            if (mag0 > 1e-30f) { float inv = 1.f/mag0; c0 = re0*inv; s0 = i0*inv; }
            else               { c0 = 1.f; s0 = 0.f; }
            float mag1 = sqrtf(re1*re1 + i1*i1);
            float c1, s1;
            if (mag1 > 1e-30f) { float inv = 1.f/mag1; c1 = re1*inv; s1 = i1*inv; }
            else               { c1 = 1.f; s1 = 0.f; }
            bsplit(mag0, g_magh[fr0*KPAD + k], g_magl[fr0*KPAD + k]);
            bsplit(mag1, g_magh[fr1*KPAD + k], g_magl[fr1*KPAD + k]);
            g_cosp[fr0*FBINS + k] = c0; g_sinp[fr0*FBINS + k] = s0;
            g_cosp[fr1*FBINS + k] = c1; g_sinp[fr1*FBINS + k] = s1;
        } else {
            __nv_bfloat16 z = __float2bfloat16(0.f);
            g_magh[fr0*KPAD + k] = z; g_magl[fr0*KPAD + k] = z;
            g_magh[fr1*KPAD + k] = z; g_magl[fr1*KPAD + k] = z;
        }
    }
}

// ================= bf16-split 3-pass tensor GEMM (validated) =================
#define SM_PLANE (128*12)
#define SM_AH(p,r,c) smem_u[((p)*128 + (r))*12 + (c)]
#define SM_AL(p,r,c) smem_u[SM_PLANE*2 + ((p)*128 + (r))*12 + (c)]
#define SM_BH(p,r,c) smem_u[SM_PLANE*4 + ((p)*128 + (r))*12 + (c)]
#define SM_BL(p,r,c) smem_u[SM_PLANE*6 + ((p)*128 + (r))*12 + (c)]
#define SMEM_GEMM_BYTES (SM_PLANE*8*4)   // 49152

template<int NIT, int KSTRIDE>
__device__ __forceinline__ void gemm_core(
    unsigned* smem_u,
    const __nv_bfloat16* Ah_g, const __nv_bfloat16* Al_g, int a_row_max,
    const __nv_bfloat16* Bh_g, const __nv_bfloat16* Bl_g,
    int m0, int n0, float acc[2][8][4])
{
    const int tid = threadIdx.x;
    const int lane = tid & 31, wid = tid >> 5;
    const int wm = wid >> 1, wn = wid & 1;
    const int grp = lane >> 2, tig = lane & 3;
    const int row = tid >> 1, half = tid & 1;
    const int arow = m0 + row;
    const int asz = (arow < a_row_max) ? 16 : 0;
    const int brow = n0 + row;

    unsigned sbase = (unsigned)__cvta_generic_to_shared(smem_u);
    unsigned off = (row*12 + half*4)*4;
    unsigned dAh = sbase + off;
    unsigned dAl = sbase + SM_PLANE*2*4 + off;
    unsigned dBh = sbase + SM_PLANE*4*4 + off;
    unsigned dBl = sbase + SM_PLANE*6*4 + off;
    const unsigned bufB = 128*12*4;

    cpa16(dAh, Ah_g + (size_t)arow*KSTRIDE + half*8, asz);
    cpa16(dAl, Al_g + (size_t)arow*KSTRIDE + half*8, asz);
    cpa16(dBh, Bh_g + (size_t)brow*KSTRIDE + half*8, 16);
    cpa16(dBl, Bl_g + (size_t)brow*KSTRIDE + half*8, 16);
    CPA_COMMIT();
    CPA_WAIT();
    __syncthreads();

    #pragma unroll 1
    for (int it = 0; it < NIT; it++) {
        int p = it & 1, q = p ^ 1;
        if (it + 1 < NIT) {
            int k0 = (it+1)*16;
            cpa16(dAh + q*bufB, Ah_g + (size_t)arow*KSTRIDE + k0 + half*8, asz);
            cpa16(dAl + q*bufB, Al_g + (size_t)arow*KSTRIDE + k0 + half*8, asz);
            cpa16(dBh + q*bufB, Bh_g + (size_t)brow*KSTRIDE + k0 + half*8, 16);
            cpa16(dBl + q*bufB, Bl_g + (size_t)brow*KSTRIDE + k0 + half*8, 16);
            CPA_COMMIT();
        }
        unsigned afh[2][4], afl[2][4];
        #pragma unroll
        for (int mt = 0; mt < 2; mt++) {
            int rA = wm*32 + mt*16 + grp;
            afh[mt][0] = SM_AH(p, rA,   tig);
            afh[mt][1] = SM_AH(p, rA+8, tig);
            afh[mt][2] = SM_AH(p, rA,   tig+4);
            afh[mt][3] = SM_AH(p, rA+8, tig+4);
            afl[mt][0] = SM_AL(p, rA,   tig);
            afl[mt][1] = SM_AL(p, rA+8, tig);
            afl[mt][2] = SM_AL(p, rA,   tig+4);
            afl[mt][3] = SM_AL(p, rA+8, tig+4);
        }
        #pragma unroll
        for (int nt = 0; nt < 8; nt++) {
            int cB = wn*64 + nt*8 + grp;
            unsigned bh0 = SM_BH(p, cB, tig);
            unsigned bh1 = SM_BH(p, cB, tig+4);
            unsigned bl0 = SM_BL(p, cB, tig);
            unsigned bl1 = SM_BL(p, cB, tig+4);
            #pragma unroll
            for (int mt = 0; mt < 2; mt++) {
                mmab(acc[mt][nt], afh[mt], bh0, bh1);
                mmab(acc[mt][nt], afh[mt], bl0, bl1);
                mmab(acc[mt][nt], afl[mt], bh0, bh1);
            }
        }
        if (it + 1 < NIT) CPA_WAIT();
        __syncthreads();
    }
}

// ---- k_xg ----
__global__ __launch_bounds__(256, 2) void k_xg() {
    extern __shared__ unsigned smem_u[];
    const int tid = threadIdx.x;
    const int lane = tid & 31, wid = tid >> 5;
    const int wm = wid >> 1, wn = wid & 1;
    const int grp = lane >> 2, tig = lane & 3;
    const int m0 = blockIdx.y * 128, n0 = blockIdx.x * 128;
    float acc[2][8][4] = {};
    gemm_core<33, KPAD>(smem_u, g_magh, g_magl, ROWS, g_wxh, g_wxl, m0, n0, acc);
    #pragma unroll
    for (int mt = 0; mt < 2; mt++) {
        #pragma unroll
        for (int nt = 0; nt < 8; nt++) {
            int row0 = m0 + wm*32 + mt*16 + grp;
            int col0 = n0 + wn*64 + nt*8 + 2*tig;
            if (row0 < ROWS) {
                int b = row0 / CPB;
                g_xg[(size_t)row0*N3H + col0  ] = acc[mt][nt][0] + g_embrow[b*N3H + col0  ];
                g_xg[(size_t)row0*N3H + col0+1] = acc[mt][nt][1] + g_embrow[b*N3H + col0+1];
            }
            int row1 = row0 + 8;
            if (row1 < ROWS) {
                int b = row1 / CPB;
                g_xg[(size_t)row1*N3H + col0  ] = acc[mt][nt][2] + g_embrow[b*N3H + col0  ];
                g_xg[(size_t)row1*N3H + col0+1] = acc[mt][nt][3] + g_embrow[b*N3H + col0+1];
            }
        }
    }
}

// ---- k_proj ----
__global__ __launch_bounds__(256, 2) void k_proj(const float* __restrict__ pb) {
    extern __shared__ unsigned smem_u[];
    const int tid = threadIdx.x;
    const int lane = tid & 31, wid = tid >> 5;
    const int wm = wid >> 1, wn = wid & 1;
    const int grp = lane >> 2, tig = lane & 3;
    const int m0 = blockIdx.y * 128, n0 = blockIdx.x * 128;
    float acc[2][8][4] = {};
    gemm_core<16, HDIM>(smem_u, g_hsh, g_hsl, ROWS, g_pwh, g_pwl, m0, n0, acc);
    #pragma unroll
    for (int mt = 0; mt < 2; mt++) {
        #pragma unroll
        for (int nt = 0; nt < 8; nt++) {
            int row0 = m0 + wm*32 + mt*16 + grp;
            int col0 = n0 + wn*64 + nt*8 + 2*tig;
            if (row0 < ROWS) {
                if (col0   < NGB) g_gb[(size_t)row0*NGB + col0  ] = acc[mt][nt][0] + pb[col0  ];
                if (col0+1 < NGB) g_gb[(size_t)row0*NGB + col0+1] = acc[mt][nt][1] + pb[col0+1];
            }
            int row1 = row0 + 8;
            if (row1 < ROWS) {
                if (col0   < NGB) g_gb[(size_t)row1*NGB + col0  ] = acc[mt][nt][2] + pb[col0  ];
                if (col0+1 < NGB) g_gb[(size_t)row1*NGB + col0+1] = acc[mt][nt][3] + pb[col0+1];
            }
        }
    }
}

// ================= per-step tensor-core GRU (16 seqs x 192 cols, BK=32) =================
// grid (4, 79) = 316 blocks, 2 blocks/SM. smem (uints):
//   AH [2buf][2kg][16row][12] @0 (768), AL @768,
//   BH [2buf][2kg][192row][12] @1536 (9216), BL @10752. Total 19968 uints = 79872 B.
// hg staging floats [16][196] aliases BH region after final sync.
#define GRS_AL 768
#define GRS_BH 1536
#define GRS_BL 10752
#define GRUS_SMEM_BYTES (19968*4)

__device__ __forceinline__ void grus_load(unsigned sbase, int p, int kc,
                                          int sq0, int g, int t) {
    const int tid = threadIdx.x;
    #pragma unroll
    for (int v = 0; v < 6; v++) {
        int slot = tid + v*256;               // 0..1535
        int plane = slot >= 768;
        int rem = plane ? slot - 768 : slot;
        int kg = rem >= 384;
        int r2 = kg ? rem - 384 : rem;
        int br = r2 >> 1, half = r2 & 1;
        int n = ((br >> 6) << 8) + g*64 + (br & 63);   // gate-natural row
        const __nv_bfloat16* src = (plane ? g_whl : g_whh)
                                   + (size_t)n*HDIM + kc*32 + kg*16 + half*8;
        unsigned dst = sbase + (unsigned)((plane ? GRS_BL : GRS_BH)
                                          + ((p*2+kg)*192 + br)*12 + half*4)*4;
        cpa16(dst, src, 16);
    }
    if (tid < 128) {
        int plane = tid >> 6;
        int rem = tid & 63;
        int kg = rem >> 5;
        int r2 = rem & 31;
        int r = r2 >> 1, half = r2 & 1;
        int sq = sq0 + r;
        int prow = sq*NF + t - 1; if (prow < 0) prow = 0;
        int sz = (t > 0 && sq < SEQ) ? 16 : 0;
        const __nv_bfloat16* src = (plane ? g_hsl : g_hsh)
                                   + (size_t)prow*HDIM + kc*32 + kg*16 + half*8;
        unsigned dst = sbase + (unsigned)((plane ? GRS_AL : 0)
                                          + ((p*2+kg)*16 + r)*12 + half*4)*4;
        cpa16(dst, src, sz);
    }
}

__global__ __launch_bounds__(256, 2) void k_gru(const float* __restrict__ gbias, int t) {
    extern __shared__ unsigned su[];
    const int tid = threadIdx.x;
    const int lane = tid & 31, wn = tid >> 5;   // 8 warps, each 24 cols (3 n8 tiles)
    const int grp = lane >> 2, tig = lane & 3;
    const int g = blockIdx.x;                   // 0..3 hidden-col group
    const int sq0 = blockIdx.y * 16;
    unsigned sbase = (unsigned)__cvta_generic_to_shared(su);

    float acc[3][4] = {};
    grus_load(sbase, 0, 0, sq0, g, t);
    CPA_COMMIT(); CPA_WAIT(); __syncthreads();
    #pragma unroll 1
    for (int kc = 0; kc < 8; kc++) {
        int p = kc & 1, q = p ^ 1;
        if (kc + 1 < 8) { grus_load(sbase, q, kc+1, sq0, g, t); CPA_COMMIT(); }
        #pragma unroll
        for (int kg = 0; kg < 2; kg++) {
            int ab = (p*2+kg)*16;
            unsigned afh[4], afl[4];
            afh[0] = su[(ab+grp)*12 + tig];
            afh[1] = su[(ab+grp+8)*12 + tig];
            afh[2] = su[(ab+grp)*12 + tig+4];
            afh[3] = su[(ab+grp+8)*12 + tig+4];
            afl[0] = su[GRS_AL + (ab+grp)*12 + tig];
            afl[1] = su[GRS_AL + (ab+grp+8)*12 + tig];
            afl[2] = su[GRS_AL + (ab+grp)*12 + tig+4];
            afl[3] = su[GRS_AL + (ab+grp+8)*12 + tig+4];
            #pragma unroll
            for (int nt = 0; nt < 3; nt++) {
                int br = wn*24 + nt*8 + grp;
                int bb = ((p*2+kg)*192 + br)*12;
                unsigned bh0 = su[GRS_BH + bb + tig];
                unsigned bh1 = su[GRS_BH + bb + tig+4];
                unsigned bl0 = su[GRS_BL + bb + tig];
                unsigned bl1 = su[GRS_BL + bb + tig+4];
                mmab(acc[nt], afh, bh0, bh1);
                mmab(acc[nt], afh, bl0, bl1);
                mmab(acc[nt], afl, bh0, bh1);
            }
        }
        if (kc + 1 < 8) CPA_WAIT();
        __syncthreads();
    }
    // stage hg floats [16][196] into BH region (all mma reads complete)
    float* hg = (float*)(su + GRS_BH);
    #pragma unroll
    for (int nt = 0; nt < 3; nt++) {
        int c0 = wn*24 + nt*8 + 2*tig;
        hg[grp*196 + c0]       = acc[nt][0];
        hg[grp*196 + c0+1]     = acc[nt][1];
        hg[(grp+8)*196 + c0]   = acc[nt][2];
        hg[(grp+8)*196 + c0+1] = acc[nt][3];
    }
    __syncthreads();
    // fused gates: 16 seqs x 64 hidden cols
    #pragma unroll
    for (int i = 0; i < 4; i++) {
        int e = tid + i*256;
        int s = e >> 6, cc = e & 63;
        int sq = sq0 + s;
        if (sq >= SEQ) continue;
        int c = g*64 + cc;
        const float* xg = g_xg + (size_t)(sq*NF + t)*N3H;
        float z = sigf(xg[c]           + hg[s*196 + cc]        + gbias[c]);
        float r = sigf(xg[HDIM + c]    + hg[s*196 + 64 + cc]   + gbias[HDIM + c]);
        float n = tanhf(xg[2*HDIM + c] + r*(hg[s*196 + 128 + cc] + gbias[2*HDIM + c]));
        float hp = 0.f;
        if (t > 0) {
            size_t pi = (size_t)(sq*NF + t - 1)*HDIM + c;
            hp = __bfloat162float(g_hsh[pi]) + __bfloat162float(g_hsl[pi]);
        }
        float h = (1.f - z)*n + z*hp;
        size_t gi = (size_t)(sq*NF + t)*HDIM + c;
        __nv_bfloat16 hh, hl;
        bsplit(h, hh, hl);
        g_hsh[gi] = hh; g_hsl[gi] = hl;
    }
}

// ---------------- modulate + inverse FFT (radix-4 core, 2 frames/block) ----------------
__global__ void k_modinv() {
    __shared__ float sre0[FBINS], sim0[FBINS], sre1[FBINS], sim1[FBINS];
    __shared__ float sr[NFFT], si[NFFT];
    __shared__ float twr[512], twi[512];
    const int pr  = blockIdx.x;
    const int tid = threadIdx.x;
    const int fr0 = 2*pr, fr1 = fr0 + 1;

    for (int k = tid; k < 512; k += 256) { twr[k] = g_twr[k]; twi[k] = g_twi[k]; }
    for (int k = tid; k < FBINS; k += 256) {
        float mag0 = __bfloat162float(g_magh[fr0*KPAD + k]) + __bfloat162float(g_magl[fr0*KPAD + k]);
        float mm0 = g_gb[(size_t)fr0*NGB + k]*mag0 + g_gb[(size_t)fr0*NGB + FBINS + k];
        sre0[k] = mm0 * g_cosp[fr0*FBINS + k];
        sim0[k] = mm0 * g_sinp[fr0*FBINS + k];
        float mag1 = __bfloat162float(g_magh[fr1*KPAD + k]) + __bfloat162float(g_magl[fr1*KPAD + k]);
        float mm1 = g_gb[(size_t)fr1*NGB + k]*mag1 + g_gb[(size_t)fr1*NGB + FBINS + k];
        sre1[k] = mm1 * g_cosp[fr1*FBINS + k];
        sim1[k] = mm1 * g_sinp[fr1*FBINS + k];
    }
    __syncthreads();
    for (int n = tid; n < NFFT; n += 256) {
        float zr, zi;
        if (n <= 512) { zr = sre0[n] - sim1[n];         zi = sim0[n] + sre1[n]; }
        else { int m = NFFT - n; zr = sre0[m] + sim1[m]; zi = sre1[m] - sim0[m]; }
        int j = __brev((unsigned)n) >> 22;
        sr[j] = zr; si[j] = zi;
    }
    __syncthreads();
    #pragma unroll
    for (int s = 1; s <= 9; s += 2) {
        const int h = 1 << (s-1);
        const int pos = tid & (h-1);
        const int grl = tid >> (s-1);
        const int base = (grl << (s+1)) + pos;
        const float wr1 = twr[pos << (10-s)], wi1 = -twi[pos << (10-s)];
        const float wr2 = twr[pos << (9-s)],  wi2 = -twi[pos << (9-s)];
        const int e3 = (pos + h) << (9-s);
        const float wr3 = twr[e3], wi3 = -twi[e3];
        float x0r = sr[base],       x0i = si[base];
        float x1r = sr[base+h],     x1i = si[base+h];
        float x2r = sr[base+2*h],   x2i = si[base+2*h];
        float x3r = sr[base+3*h],   x3i = si[base+3*h];
        float t1r = wr1*x1r - wi1*x1i, t1i = wr1*x1i + wi1*x1r;
        float u0r = x0r + t1r, u0i = x0i + t1i;
        float u1r = x0r - t1r, u1i = x0i - t1i;
        float t3r = wr1*x3r - wi1*x3i, t3i = wr1*x3i + wi1*x3r;
        float u2r = x2r + t3r, u2i = x2i + t3i;
        float u3r = x2r - t3r, u3i = x2i - t3i;
        float v2r = wr2*u2r - wi2*u2i, v2i = wr2*u2i + wi2*u2r;
        float v3r = wr3*u3r - wi3*u3i, v3i = wr3*u3i + wi3*u3r;
        sr[base]       = u0r + v2r; si[base]       = u0i + v2i;
        sr[base+2*h]   = u0r - v2r; si[base+2*h]   = u0i - v2i;
        sr[base+h]     = u1r + v3r; si[base+h]     = u1i + v3i;
        sr[base+3*h]   = u1r - v3r; si[base+3*h]   = u1i - v3i;
        __syncthreads();
    }
    const float invn = 1.f/(float)NFFT;
    for (int n = tid; n < NFFT; n += 256) {
        float w = invn*g_win[n];
        g_y[(size_t)fr0*NFFT + n] = sr[n]*w;
        g_y[(size_t)fr1*NFFT + n] = si[n]*w;
    }
}

// ---------------- overlap-add ----------------
__global__ void k_overlap(float* __restrict__ out) {
    const int t = blockIdx.x*blockDim.x + threadIdx.x;
    const int b = blockIdx.y;
    if (t >= TSZ) return;
    int ci_hi = t / STRIDE; if (ci_hi > NCH-1) ci_hi = NCH-1;
    int v = t - (CHUNK - 1);
    int ci_lo = (v <= 0) ? 0 : (v + STRIDE - 1)/STRIDE;
    float acc = 0.f;
    for (int ci = ci_lo; ci <= ci_hi; ci++) {
        int n = t - ci*STRIDE;
        int fi_hi = n >> 8; if (fi_hi > NF-1) fi_hi = NF-1;
        int w = n - (NFFT - 1);
        int fi_lo = (w <= 0) ? 0 : (w + HOP - 1) >> 8;
        float s = 0.f;
        for (int fi = fi_lo; fi <= fi_hi; fi++)
            s += g_y[(size_t)(((b*NCH + ci)*NF) + fi)*NFFT + n - fi*HOP];
        acc += s / fmaxf(g_wsum[n], 1e-8f);
    }
    out[b*TSZ + t] = acc;
}

// ---------------- launch ----------------
extern "C" void kernel_launch(void* const* d_in, const int* in_sizes, int n_in,
                              void* d_out, int out_size) {
    const float* audio     = (const float*)d_in[0];
    const float* emb_table = (const float*)d_in[1];
    const float* gru_wx    = (const float*)d_in[2];
    const float* gru_wh    = (const float*)d_in[3];
    const float* gru_b     = (const float*)d_in[4];
    const float* proj_w    = (const float*)d_in[5];
    const float* proj_b    = (const float*)d_in[6];
    const int*   effect_id = (const int*)  d_in[7];
    float* out = (float*)d_out;

    cudaFuncSetAttribute(k_gru, cudaFuncAttributeMaxDynamicSharedMemorySize,
                         GRUS_SMEM_BYTES);   // idempotent host-side call

    k_prep<<<PB_TAB + PB_WX + PB_PW + PB_WH + BATCH, 256>>>(
        gru_wx, proj_w, gru_wh, emb_table, effect_id);                        // 1
    k_fwdfft<<<ROWS/2, 256>>>(audio);                                         // 2
    k_xg<<<dim3(N3H/128, (ROWS + 127)/128), 256, SMEM_GEMM_BYTES>>>();        // 3
    for (int t = 0; t < NF; t++)                                              // 4.. (slot 4 = t=0)
        k_gru<<<dim3(4, (SEQ + 15)/16), 256, GRUS_SMEM_BYTES>>>(gru_b, t);
    k_proj<<<dim3(PWLD/128, (ROWS + 127)/128), 256, SMEM_GEMM_BYTES>>>(proj_b);
    k_modinv<<<ROWS/2, 256>>>();
    k_overlap<<<dim3((TSZ + 255)/256, BATCH), 256>>>(out);
}